// round 1
// baseline (speedup 1.0000x reference)
#include <cuda_runtime.h>
#include <cuda_bf16.h>

// Problem constants
#define Bb 2
#define Ss 2048
#define Ee 1024
#define Hh 16
#define Dd 64
#define Mm (Bb*Ss)          // 4096 rows (tokens)
// NORM = sqrt(E) = 32

// ---------------------------------------------------------------------------
// Scratch (static __device__ globals; allocation inside kernel_launch is banned)
// ---------------------------------------------------------------------------
__device__ float g_q[Mm * Ee];
__device__ float g_k[Mm * Ee];
__device__ float g_v[Mm * Ee];
__device__ float g_g[Bb * Hh * Ss];   // diagonal softmax gate

// ---------------------------------------------------------------------------
// FFMA-only exp (Taylor 2^f on [-0.5,0.5]); args here are in ~[-2,2]
// ---------------------------------------------------------------------------
__device__ __forceinline__ float fast_exp(float x) {
    float t = x * 1.4426950408889634f;       // x * log2(e)
    int   e = __float2int_rn(t);
    float f = t - (float)e;
    float p = 0.0013333558146428443f;
    p = fmaf(p, f, 0.009618129842126066f);
    p = fmaf(p, f, 0.05550410866482158f);
    p = fmaf(p, f, 0.2402265069591007f);
    p = fmaf(p, f, 0.6931471805599453f);
    p = fmaf(p, f, 1.0f);
    return p * __int_as_float((e + 127) << 23);
}

// ---------------------------------------------------------------------------
// GEMM 1: q/k/v = x @ W^T   (C[m,n] = sum_k A[m,k] * W[n,k])
// BM=BN=128, BK=16, 256 threads, 8x8 per thread. blockIdx.z selects q/k/v.
// ---------------------------------------------------------------------------
__global__ void __launch_bounds__(256) gemm_qkv(const float* __restrict__ X,
                                                const float* __restrict__ Wq,
                                                const float* __restrict__ Wk,
                                                const float* __restrict__ Wv)
{
    __shared__ float As[16][132];
    __shared__ float Bs[16][132];

    const float* W = (blockIdx.z == 0) ? Wq : (blockIdx.z == 1) ? Wk : Wv;
    float*       C = (blockIdx.z == 0) ? g_q : (blockIdx.z == 1) ? g_k : g_v;

    const int tid = threadIdx.x;
    const int tx = tid & 15, ty = tid >> 4;
    const int m0 = blockIdx.y * 128, n0 = blockIdx.x * 128;

    float acc[8][8];
#pragma unroll
    for (int i = 0; i < 8; i++)
#pragma unroll
        for (int j = 0; j < 8; j++) acc[i][j] = 0.f;

    for (int k0 = 0; k0 < Ee; k0 += 16) {
#pragma unroll
        for (int it = 0; it < 2; it++) {
            int idx = tid + it * 256;       // 0..511
            int r   = idx >> 2;             // 0..127
            int c4  = (idx & 3) << 2;       // 0,4,8,12
            float4 va = *(const float4*)&X[(size_t)(m0 + r) * Ee + k0 + c4];
            As[c4 + 0][r] = va.x; As[c4 + 1][r] = va.y;
            As[c4 + 2][r] = va.z; As[c4 + 3][r] = va.w;
            float4 vb = *(const float4*)&W[(size_t)(n0 + r) * Ee + k0 + c4];
            Bs[c4 + 0][r] = vb.x; Bs[c4 + 1][r] = vb.y;
            Bs[c4 + 2][r] = vb.z; Bs[c4 + 3][r] = vb.w;
        }
        __syncthreads();
#pragma unroll
        for (int kk = 0; kk < 16; kk++) {
            float4 a0 = *(const float4*)&As[kk][ty * 8];
            float4 a1 = *(const float4*)&As[kk][ty * 8 + 4];
            float4 b0 = *(const float4*)&Bs[kk][tx * 8];
            float4 b1 = *(const float4*)&Bs[kk][tx * 8 + 4];
            float ra[8] = {a0.x, a0.y, a0.z, a0.w, a1.x, a1.y, a1.z, a1.w};
            float rb[8] = {b0.x, b0.y, b0.z, b0.w, b1.x, b1.y, b1.z, b1.w};
#pragma unroll
            for (int i = 0; i < 8; i++)
#pragma unroll
                for (int j = 0; j < 8; j++)
                    acc[i][j] = fmaf(ra[i], rb[j], acc[i][j]);
        }
        __syncthreads();
    }

#pragma unroll
    for (int i = 0; i < 8; i++) {
        int row = m0 + ty * 8 + i;
        float4 o0 = {acc[i][0], acc[i][1], acc[i][2], acc[i][3]};
        float4 o1 = {acc[i][4], acc[i][5], acc[i][6], acc[i][7]};
        *(float4*)&C[(size_t)row * Ee + n0 + tx * 8]     = o0;
        *(float4*)&C[(size_t)row * Ee + n0 + tx * 8 + 4] = o1;
    }
}

// ---------------------------------------------------------------------------
// Score pass: per (b,h,qtile of 64 rows), loop causal k-tiles; accumulate
// row sums of exp(q.k/32) and capture the diagonal term. No max-subtraction:
// logits ~ N(0, 0.25), exp is safe.
// grid = (32 qtiles, 16 heads, 2 batch), 256 threads (16x16, 4x4 micro-tile)
// ---------------------------------------------------------------------------
__global__ void __launch_bounds__(256) score_kernel()
{
    __shared__ float Qs[64][68];
    __shared__ float Ks[64][68];

    const int qt = blockIdx.x, h = blockIdx.y, b = blockIdx.z;
    const int tid = threadIdx.x;
    const int tx = tid & 15, ty = tid >> 4;

    // load Q tile transposed: Qs[d][s_loc]
#pragma unroll
    for (int it = 0; it < 4; it++) {
        int idx = tid + it * 256;            // 0..1023
        int r   = idx >> 4;                  // 0..63
        int d4  = (idx & 15) * 4;
        int row = b * Ss + qt * 64 + r;
        float4 v = *(const float4*)&g_q[(size_t)row * Ee + h * Dd + d4];
        Qs[d4 + 0][r] = v.x; Qs[d4 + 1][r] = v.y;
        Qs[d4 + 2][r] = v.z; Qs[d4 + 3][r] = v.w;
    }

    float rowpart[4] = {0.f, 0.f, 0.f, 0.f};
    float diag[4]    = {0.f, 0.f, 0.f, 0.f};

    for (int kt = 0; kt <= qt; kt++) {
        __syncthreads();   // protect Ks from previous iteration readers
#pragma unroll
        for (int it = 0; it < 4; it++) {
            int idx = tid + it * 256;
            int r   = idx >> 4;
            int d4  = (idx & 15) * 4;
            int row = b * Ss + kt * 64 + r;
            float4 v = *(const float4*)&g_k[(size_t)row * Ee + h * Dd + d4];
            Ks[d4 + 0][r] = v.x; Ks[d4 + 1][r] = v.y;
            Ks[d4 + 2][r] = v.z; Ks[d4 + 3][r] = v.w;
        }
        __syncthreads();

        float sc[4][4];
#pragma unroll
        for (int i = 0; i < 4; i++)
#pragma unroll
            for (int j = 0; j < 4; j++) sc[i][j] = 0.f;

#pragma unroll
        for (int d = 0; d < 64; d++) {
            float4 a = *(const float4*)&Qs[d][ty * 4];
            float4 k4 = *(const float4*)&Ks[d][tx * 4];
            float ra[4] = {a.x, a.y, a.z, a.w};
            float rk[4] = {k4.x, k4.y, k4.z, k4.w};
#pragma unroll
            for (int i = 0; i < 4; i++)
#pragma unroll
                for (int j = 0; j < 4; j++)
                    sc[i][j] = fmaf(ra[i], rk[j], sc[i][j]);
        }

        const bool diagTile = (kt == qt);
#pragma unroll
        for (int i = 0; i < 4; i++) {
#pragma unroll
            for (int j = 0; j < 4; j++) {
                float val = sc[i][j] * 0.03125f;      // /32 = /sqrt(E)
                int iloc = ty * 4 + i, jloc = tx * 4 + j;
                float e;
                if (diagTile && jloc > iloc) {
                    e = 0.f;                          // causal mask
                } else {
                    e = fast_exp(val);
                }
                if (diagTile && jloc == iloc) diag[i] = e;
                rowpart[i] += e;
            }
        }
    }

    // reduce row sums across the 16 tx lanes (within 16-lane half-warp)
#pragma unroll
    for (int i = 0; i < 4; i++) {
        float s = rowpart[i];
        s += __shfl_xor_sync(0xffffffffu, s, 8, 16);
        s += __shfl_xor_sync(0xffffffffu, s, 4, 16);
        s += __shfl_xor_sync(0xffffffffu, s, 2, 16);
        s += __shfl_xor_sync(0xffffffffu, s, 1, 16);
        rowpart[i] = s;
    }

    if (tx == ty) {
#pragma unroll
        for (int i = 0; i < 4; i++) {
            int s = qt * 64 + ty * 4 + i;
            g_g[((size_t)b * Hh + h) * Ss + s] = diag[i] / rowpart[i];
        }
    }
}

// ---------------------------------------------------------------------------
// GEMM 2: out = (g ⊙ v) @ Wo^T + v
// Same tiling as gemm_qkv; A-load multiplies by the per-(token,head) gate,
// epilogue adds the residual v.
// ---------------------------------------------------------------------------
__global__ void __launch_bounds__(256) gemm_out(const float* __restrict__ Wo,
                                                float* __restrict__ Out)
{
    __shared__ float As[16][132];
    __shared__ float Bs[16][132];

    const int tid = threadIdx.x;
    const int tx = tid & 15, ty = tid >> 4;
    const int m0 = blockIdx.y * 128, n0 = blockIdx.x * 128;

    float acc[8][8];
#pragma unroll
    for (int i = 0; i < 8; i++)
#pragma unroll
        for (int j = 0; j < 8; j++) acc[i][j] = 0.f;

    for (int k0 = 0; k0 < Ee; k0 += 16) {
        const int h = k0 >> 6;    // whole 16-wide k-tile sits in one head block
#pragma unroll
        for (int it = 0; it < 2; it++) {
            int idx = tid + it * 256;
            int r   = idx >> 2;
            int c4  = (idx & 3) << 2;
            int row = m0 + r;
            float gv = g_g[(((size_t)(row >> 11) << 4) | h) * Ss + (row & 2047)];
            float4 va = *(const float4*)&g_v[(size_t)row * Ee + k0 + c4];
            As[c4 + 0][r] = va.x * gv; As[c4 + 1][r] = va.y * gv;
            As[c4 + 2][r] = va.z * gv; As[c4 + 3][r] = va.w * gv;
            float4 vb = *(const float4*)&Wo[(size_t)(n0 + r) * Ee + k0 + c4];
            Bs[c4 + 0][r] = vb.x; Bs[c4 + 1][r] = vb.y;
            Bs[c4 + 2][r] = vb.z; Bs[c4 + 3][r] = vb.w;
        }
        __syncthreads();
#pragma unroll
        for (int kk = 0; kk < 16; kk++) {
            float4 a0 = *(const float4*)&As[kk][ty * 8];
            float4 a1 = *(const float4*)&As[kk][ty * 8 + 4];
            float4 b0 = *(const float4*)&Bs[kk][tx * 8];
            float4 b1 = *(const float4*)&Bs[kk][tx * 8 + 4];
            float ra[8] = {a0.x, a0.y, a0.z, a0.w, a1.x, a1.y, a1.z, a1.w};
            float rb[8] = {b0.x, b0.y, b0.z, b0.w, b1.x, b1.y, b1.z, b1.w};
#pragma unroll
            for (int i = 0; i < 8; i++)
#pragma unroll
                for (int j = 0; j < 8; j++)
                    acc[i][j] = fmaf(ra[i], rb[j], acc[i][j]);
        }
        __syncthreads();
    }

#pragma unroll
    for (int i = 0; i < 8; i++) {
        int row = m0 + ty * 8 + i;
        float4 s0 = *(const float4*)&g_v[(size_t)row * Ee + n0 + tx * 8];
        float4 s1 = *(const float4*)&g_v[(size_t)row * Ee + n0 + tx * 8 + 4];
        float4 o0 = {acc[i][0] + s0.x, acc[i][1] + s0.y,
                     acc[i][2] + s0.z, acc[i][3] + s0.w};
        float4 o1 = {acc[i][4] + s1.x, acc[i][5] + s1.y,
                     acc[i][6] + s1.z, acc[i][7] + s1.w};
        *(float4*)&Out[(size_t)row * Ee + n0 + tx * 8]     = o0;
        *(float4*)&Out[(size_t)row * Ee + n0 + tx * 8 + 4] = o1;
    }
}

// ---------------------------------------------------------------------------
extern "C" void kernel_launch(void* const* d_in, const int* in_sizes, int n_in,
                              void* d_out, int out_size)
{
    const float* x  = (const float*)d_in[0];
    const float* wq = (const float*)d_in[1];
    const float* wk = (const float*)d_in[2];
    const float* wv = (const float*)d_in[3];
    const float* wo = (const float*)d_in[4];
    float* out = (float*)d_out;

    dim3 gQKV(Ee / 128, Mm / 128, 3);
    gemm_qkv<<<gQKV, 256>>>(x, wq, wk, wv);

    dim3 gS(Ss / 64, Hh, Bb);
    score_kernel<<<gS, 256>>>();

    dim3 gO(Ee / 128, Mm / 128);
    gemm_out<<<gO, 256>>>(wo, out);
}

// round 5
// speedup vs baseline: 3.2848x; 3.2848x over previous
#include <cuda_runtime.h>
#include <cstdint>
#include <cstddef>

#define Bb 2
#define Ss 2048
#define Ee 1024
#define Hh 16
#define Dd 64
#define Mm (Bb*Ss)

// ---------------------------------------------------------------------------
// Scratch
// ---------------------------------------------------------------------------
__device__ float g_q[Mm * Ee];
__device__ float g_k[Mm * Ee];
__device__ float g_v[Mm * Ee];
__device__ float g_g[Bb * Hh * Ss];

// ---------------------------------------------------------------------------
// Helpers (family-agnostic PTX only: cp.async, ldmatrix, mma.sync — sm_80+)
// ---------------------------------------------------------------------------
__device__ __forceinline__ uint32_t smem_u32(const void* p) {
    uint32_t a;
    asm("{ .reg .u64 t; cvta.to.shared.u64 t, %1; cvt.u32.u64 %0, t; }"
        : "=r"(a) : "l"(p));
    return a;
}
__device__ __forceinline__ void cpa16(uint32_t s, const void* g) {
    asm volatile("cp.async.cg.shared.global [%0], [%1], 16;" :: "r"(s), "l"(g));
}
__device__ __forceinline__ void cpa_commit() {
    asm volatile("cp.async.commit_group;" ::: "memory");
}
template<int N> __device__ __forceinline__ void cpa_wait() {
    asm volatile("cp.async.wait_group %0;" :: "n"(N) : "memory");
}
__device__ __forceinline__ void ldsm4(uint32_t& r0, uint32_t& r1,
                                      uint32_t& r2, uint32_t& r3, uint32_t addr) {
    asm volatile("ldmatrix.sync.aligned.m8n8.x4.shared.b16 {%0,%1,%2,%3}, [%4];"
                 : "=r"(r0), "=r"(r1), "=r"(r2), "=r"(r3) : "r"(addr));
}
__device__ __forceinline__ void mma8(float* c, const uint32_t* a,
                                     uint32_t b0, uint32_t b1) {
    asm volatile(
        "mma.sync.aligned.m16n8k8.row.col.f32.tf32.tf32.f32 "
        "{%0,%1,%2,%3}, {%4,%5,%6,%7}, {%8,%9}, {%0,%1,%2,%3};"
        : "+f"(c[0]), "+f"(c[1]), "+f"(c[2]), "+f"(c[3])
        : "r"(a[0]), "r"(a[1]), "r"(a[2]), "r"(a[3]), "r"(b0), "r"(b1));
}

// FFMA-only exp
__device__ __forceinline__ float fast_exp(float x) {
    float t = x * 1.4426950408889634f;
    int   e = __float2int_rn(t);
    float f = t - (float)e;
    float p = 0.0013333558146428443f;
    p = fmaf(p, f, 0.009618129842126066f);
    p = fmaf(p, f, 0.05550410866482158f);
    p = fmaf(p, f, 0.2402265069591007f);
    p = fmaf(p, f, 0.6931471805599453f);
    p = fmaf(p, f, 1.0f);
    return p * __int_as_float((e + 127) << 23);
}

// ---------------------------------------------------------------------------
// Dense GEMM core: C[128x128] = A[128xK] @ Bw[128xK]^T (+Resid)
// 256 threads (8 warps, 2x4). Warp tile 64x32. BK=32, 4-stage cp.async.
// SMEM stage: A 128x32 (16KB, swizzled) | B 128x32 (16KB).
// ---------------------------------------------------------------------------
template<bool RES>
__device__ __forceinline__ void gemm_core(const float* __restrict__ A,
                                          const float* __restrict__ Bw,
                                          float* __restrict__ C,
                                          const float* __restrict__ Resid,
                                          int m0, int n0, char* dsm)
{
    const uint32_t stg = smem_u32(dsm);
    const int tid = threadIdx.x;
    const int wid = tid >> 5, lane = tid & 31;
    const int wr = wid >> 2, wc = wid & 3;

    auto load_stage = [&](int kb) {
        uint32_t s = stg + (uint32_t)(kb & 3) * 32768u;
        int k0 = kb * 32;
#pragma unroll
        for (int i = 0; i < 8; i++) {
            int j     = tid + i * 256;     // 0..2047
            int which = j >> 10;           // 0:A 1:B
            int idx   = j & 1023;
            int r     = idx >> 3;          // 0..127
            int ch    = idx & 7;           // 16B chunk
            uint32_t dst = s + (uint32_t)which * 16384u
                         + (uint32_t)r * 128u + ((uint32_t)(ch ^ (r & 7)) << 4);
            const float* src = which ? &Bw[(size_t)(n0 + r) * Ee + k0 + ch * 4]
                                     : &A [(size_t)(m0 + r) * Ee + k0 + ch * 4];
            cpa16(dst, src);
        }
        cpa_commit();
    };

    float acc[4][4][4];
#pragma unroll
    for (int i = 0; i < 4; i++)
#pragma unroll
        for (int j = 0; j < 4; j++)
#pragma unroll
            for (int k = 0; k < 4; k++) acc[i][j][k] = 0.f;

    load_stage(0); load_stage(1); load_stage(2);

    const int rA = wr * 64 + (lane & 15);                         // + mi*16
    const int cAbit = lane >> 4;                                  // 0/1
    const int rB = wc * 32 + (lane & 7) + ((lane >> 4) << 3);     // + njp*16
    const int cBbit = (lane >> 3) & 1;

    for (int kb = 0; kb < 32; ++kb) {
        int rem = 31 - kb;
        if (rem >= 2)      cpa_wait<2>();
        else if (rem == 1) cpa_wait<1>();
        else               cpa_wait<0>();
        __syncthreads();
        if (kb + 3 < 32) load_stage(kb + 3);

        uint32_t As = stg + (uint32_t)(kb & 3) * 32768u;
        uint32_t Bs = As + 16384u;
#pragma unroll
        for (int s8 = 0; s8 < 4; ++s8) {
            uint32_t a[4][4];
#pragma unroll
            for (int mi = 0; mi < 4; mi++) {
                int row = rA + mi * 16;
                int ch  = 2 * s8 + cAbit;
                uint32_t addr = As + (uint32_t)row * 128u
                              + ((uint32_t)(ch ^ (row & 7)) << 4);
                ldsm4(a[mi][0], a[mi][1], a[mi][2], a[mi][3], addr);
            }
            uint32_t b[2][4];
#pragma unroll
            for (int njp = 0; njp < 2; njp++) {
                int row = rB + njp * 16;
                int ch  = 2 * s8 + cBbit;
                uint32_t addr = Bs + (uint32_t)row * 128u
                              + ((uint32_t)(ch ^ (row & 7)) << 4);
                ldsm4(b[njp][0], b[njp][1], b[njp][2], b[njp][3], addr);
            }
#pragma unroll
            for (int mi = 0; mi < 4; mi++)
#pragma unroll
                for (int nj = 0; nj < 4; nj++)
                    mma8(acc[mi][nj], a[mi],
                         b[nj >> 1][(nj & 1) * 2], b[nj >> 1][(nj & 1) * 2 + 1]);
        }
    }

    // epilogue: c0:(g,2t) c1:(g,2t+1) c2:(g+8,2t) c3:(g+8,2t+1)
#pragma unroll
    for (int mi = 0; mi < 4; mi++) {
        int r0 = m0 + wr * 64 + mi * 16 + (lane >> 2);
#pragma unroll
        for (int nj = 0; nj < 4; nj++) {
            int c0 = n0 + wc * 32 + nj * 8 + 2 * (lane & 3);
            float2 v0 = {acc[mi][nj][0], acc[mi][nj][1]};
            float2 v1 = {acc[mi][nj][2], acc[mi][nj][3]};
            if (RES) {
                float2 a0 = *(const float2*)&Resid[(size_t)r0 * Ee + c0];
                float2 a1 = *(const float2*)&Resid[(size_t)(r0 + 8) * Ee + c0];
                v0.x += a0.x; v0.y += a0.y; v1.x += a1.x; v1.y += a1.y;
            }
            *(float2*)&C[(size_t)r0 * Ee + c0]       = v0;
            *(float2*)&C[(size_t)(r0 + 8) * Ee + c0] = v1;
        }
    }
}

__global__ void __launch_bounds__(256, 1)
tc_qkv(const float* __restrict__ X, const float* __restrict__ Wq,
       const float* __restrict__ Wk, const float* __restrict__ Wv)
{
    extern __shared__ char dsm[];
    const float* W = (blockIdx.z == 0) ? Wq : (blockIdx.z == 1) ? Wk : Wv;
    float*       C = (blockIdx.z == 0) ? g_q : (blockIdx.z == 1) ? g_k : g_v;
    gemm_core<false>(X, W, C, nullptr, blockIdx.y * 128, blockIdx.x * 128, dsm);
}

__global__ void __launch_bounds__(256, 1)
tc_out(const float* __restrict__ Wo, float* __restrict__ Out)
{
    extern __shared__ char dsm[];
    gemm_core<true>(g_q, Wo, Out, g_v, blockIdx.y * 128, blockIdx.x * 128, dsm);
}

// ---------------------------------------------------------------------------
// Score pass: per (b,h,qtile=128 rows): for each causal kt tile compute
// S = Q[128x64] @ K[128x64]^T via mma, exp+mask in registers, row sums
// accumulated across tiles. Gate g = diag / rowsum.
// SMEM: Q 32KB + 3 K stages x 32KB + reduce arrays.
// ---------------------------------------------------------------------------
__global__ void __launch_bounds__(256, 1)
tc_score()
{
    extern __shared__ char dsm[];
    const uint32_t base = smem_u32(dsm);
    const uint32_t Qs = base;
    const uint32_t Ks = base + 32768u;
    float* sSum  = (float*)(dsm + 131072);
    float* sDiag = (float*)(dsm + 131072 + 512);

    const int qt = blockIdx.x, h = blockIdx.y, b = blockIdx.z;
    const int tid = threadIdx.x;
    const int wid = tid >> 5, lane = tid & 31;
    const int wr = wid >> 2, wc = wid & 3;

    auto load_q = [&]() {
#pragma unroll
        for (int i = 0; i < 8; i++) {
            int j  = tid + i * 256;     // 0..2047
            int r  = j >> 4;            // 0..127
            int ch = j & 15;            // 16 chunks (64 floats/row)
            uint32_t dst = Qs + (uint32_t)r * 256u + ((uint32_t)(ch ^ (r & 7)) << 4);
            cpa16(dst, &g_q[(size_t)(b * Ss + qt * 128 + r) * Ee + h * Dd + ch * 4]);
        }
    };
    auto load_k = [&](int kt, int slot) {
        uint32_t s = Ks + (uint32_t)slot * 32768u;
#pragma unroll
        for (int i = 0; i < 8; i++) {
            int j  = tid + i * 256;
            int r  = j >> 4;
            int ch = j & 15;
            uint32_t dst = s + (uint32_t)r * 256u + ((uint32_t)(ch ^ (r & 7)) << 4);
            cpa16(dst, &g_k[(size_t)(b * Ss + kt * 128 + r) * Ee + h * Dd + ch * 4]);
        }
    };

    load_q(); load_k(0, 0); cpa_commit();
    if (qt >= 1) { load_k(1, 1); cpa_commit(); }

    if (tid < 128) { sSum[tid] = 0.f; sDiag[tid] = 0.f; }

    float rs[8], dv[8];
#pragma unroll
    for (int k = 0; k < 8; k++) { rs[k] = 0.f; dv[k] = 0.f; }

    const int rA = wr * 64 + (lane & 15);
    const int cAbit = lane >> 4;
    const int rB = wc * 32 + (lane & 7) + ((lane >> 4) << 3);
    const int cBbit = (lane >> 3) & 1;

    for (int kt = 0; kt <= qt; ++kt) {
        if (kt == qt) cpa_wait<0>(); else cpa_wait<1>();
        __syncthreads();
        if (kt + 2 <= qt) { load_k(kt + 2, (kt + 2) % 3); cpa_commit(); }

        float acc[4][4][4];
#pragma unroll
        for (int i = 0; i < 4; i++)
#pragma unroll
            for (int j = 0; j < 4; j++)
#pragma unroll
                for (int k = 0; k < 4; k++) acc[i][j][k] = 0.f;

        uint32_t Ksl = Ks + (uint32_t)(kt % 3) * 32768u;
#pragma unroll
        for (int s8 = 0; s8 < 8; ++s8) {
            uint32_t a[4][4];
#pragma unroll
            for (int mi = 0; mi < 4; mi++) {
                int row = rA + mi * 16;
                int ch  = 2 * s8 + cAbit;
                uint32_t addr = Qs + (uint32_t)row * 256u
                              + ((uint32_t)(ch ^ (row & 7)) << 4);
                ldsm4(a[mi][0], a[mi][1], a[mi][2], a[mi][3], addr);
            }
            uint32_t bfr[2][4];
#pragma unroll
            for (int njp = 0; njp < 2; njp++) {
                int row = rB + njp * 16;
                int ch  = 2 * s8 + cBbit;
                uint32_t addr = Ksl + (uint32_t)row * 256u
                              + ((uint32_t)(ch ^ (row & 7)) << 4);
                ldsm4(bfr[njp][0], bfr[njp][1], bfr[njp][2], bfr[njp][3], addr);
            }
#pragma unroll
            for (int mi = 0; mi < 4; mi++)
#pragma unroll
                for (int nj = 0; nj < 4; nj++)
                    mma8(acc[mi][nj], a[mi],
                         bfr[nj >> 1][(nj & 1) * 2], bfr[nj >> 1][(nj & 1) * 2 + 1]);
        }

        const bool dt = (kt == qt);
#pragma unroll
        for (int mi = 0; mi < 4; mi++) {
            int il0 = wr * 64 + mi * 16 + (lane >> 2);
#pragma unroll
            for (int nj = 0; nj < 4; nj++) {
                int jl = wc * 32 + nj * 8 + 2 * (lane & 3);
#pragma unroll
                for (int q = 0; q < 4; q++) {
                    int il = il0 + (q >> 1) * 8;
                    int j  = jl  + (q & 1);
                    float e = fast_exp(acc[mi][nj][q] * 0.03125f);
                    if (dt) {
                        if (j > il)  e = 0.f;
                        if (j == il) dv[mi * 2 + (q >> 1)] = e;
                    }
                    rs[mi * 2 + (q >> 1)] += e;
                }
            }
        }
    }

    // quad reduce (lanes in a quad share rows)
#pragma unroll
    for (int k = 0; k < 8; k++) {
        rs[k] += __shfl_xor_sync(0xffffffffu, rs[k], 1);
        rs[k] += __shfl_xor_sync(0xffffffffu, rs[k], 2);
        dv[k] += __shfl_xor_sync(0xffffffffu, dv[k], 1);
        dv[k] += __shfl_xor_sync(0xffffffffu, dv[k], 2);
    }
    if ((lane & 3) == 0) {
#pragma unroll
        for (int k = 0; k < 8; k++) {
            int row = wr * 64 + (k >> 1) * 16 + (k & 1) * 8 + (lane >> 2);
            atomicAdd(&sSum[row], rs[k]);
            atomicAdd(&sDiag[row], dv[k]);
        }
    }
    __syncthreads();
    if (tid < 128)
        g_g[((size_t)b * Hh + h) * Ss + qt * 128 + tid] = sDiag[tid] / sSum[tid];
}

// ---------------------------------------------------------------------------
// gv = g ⊙ v  (into g_q; q is dead after the score pass)
// ---------------------------------------------------------------------------
__global__ void __launch_bounds__(256) gv_prep()
{
    int row = blockIdx.x;
    int tid = threadIdx.x;
    int b = row >> 11, s = row & 2047;
    int h = tid >> 4;
    float gval = g_g[((size_t)(b * Hh + h)) * Ss + s];
    float4 v = *(const float4*)&g_v[(size_t)row * Ee + tid * 4];
    v.x *= gval; v.y *= gval; v.z *= gval; v.w *= gval;
    *(float4*)&g_q[(size_t)row * Ee + tid * 4] = v;
}

// ---------------------------------------------------------------------------
extern "C" void kernel_launch(void* const* d_in, const int* in_sizes, int n_in,
                              void* d_out, int out_size)
{
    const float* x  = (const float*)d_in[0];
    const float* wq = (const float*)d_in[1];
    const float* wk = (const float*)d_in[2];
    const float* wv = (const float*)d_in[3];
    const float* wo = (const float*)d_in[4];
    float* out = (float*)d_out;

    const int SMEM_GEMM  = 4 * 32768;            // 131072
    const int SMEM_SCORE = 4 * 32768 + 1024;     // Q + 3 K stages + reduce

    static int inited = 0;
    cudaFuncSetAttribute(tc_qkv,   cudaFuncAttributeMaxDynamicSharedMemorySize, SMEM_GEMM);
    cudaFuncSetAttribute(tc_out,   cudaFuncAttributeMaxDynamicSharedMemorySize, SMEM_GEMM);
    cudaFuncSetAttribute(tc_score, cudaFuncAttributeMaxDynamicSharedMemorySize, SMEM_SCORE);
    (void)inited;

    tc_qkv<<<dim3(Ee / 128, Mm / 128, 3), 256, SMEM_GEMM>>>(x, wq, wk, wv);
    tc_score<<<dim3(Ss / 128, Hh, Bb), 256, SMEM_SCORE>>>();
    gv_prep<<<Mm, 256>>>();
    tc_out<<<dim3(Ee / 128, Mm / 128), 256, SMEM_GEMM>>>(wo, out);
}